// round 6
// baseline (speedup 1.0000x reference)
#include <cuda_runtime.h>
#include <cuda_bf16.h>
#include <math.h>

// ---------------- problem constants ----------------
#define B_  32
#define C_  64
#define D_  128
#define HID 256
#define HW_ 64
#define NPIX 4096
#define TOT1 36864
#define NSTEP 32

// ---------------- device scratch ----------------
__device__ float g_h2[B_][HID];
__device__ float g_film[4][B_][C_];   // g1, be1, g2, be2
// bf16 hi/lo weight planes: [which][b][cc(4)][tap(9)][co(64)][ci16]
__device__ __nv_bfloat16 g_wh[2][B_][4 * 9 * C_ * 16];
__device__ __nv_bfloat16 g_wl[2][B_][4 * 9 * C_ * 16];
// activation planes: [b][cc(4)][y][x][ci16]
__device__ __nv_bfloat16 g_sh[(size_t)B_ * 4 * NPIX * 16];  // state (hi)
__device__ __nv_bfloat16 g_sl[(size_t)B_ * 4 * NPIX * 16];  // state (lo)
__device__ __nv_bfloat16 g_uh[(size_t)B_ * 4 * NPIX * 16];  // intermediate (hi)
__device__ __nv_bfloat16 g_ul[(size_t)B_ * 4 * NPIX * 16];  // intermediate (lo)
__device__ float g_X[(size_t)B_ * C_ * NPIX];               // f32 state (blend source), NCHW

// ---------------- PTX helpers ----------------
__device__ __forceinline__ unsigned smem_u32(const void* p) {
    return (unsigned)__cvta_generic_to_shared(p);
}
__device__ __forceinline__ void ldsm4(unsigned* r, unsigned addr) {
    asm volatile("ldmatrix.sync.aligned.m8n8.x4.shared.b16 {%0,%1,%2,%3}, [%4];"
        : "=r"(r[0]), "=r"(r[1]), "=r"(r[2]), "=r"(r[3]) : "r"(addr));
}
__device__ __forceinline__ void mma16816(float* d, const unsigned* a,
                                         unsigned b0, unsigned b1) {
    asm volatile("mma.sync.aligned.m16n8k16.row.col.f32.bf16.bf16.f32 "
                 "{%0,%1,%2,%3}, {%4,%5,%6,%7}, {%8,%9}, {%0,%1,%2,%3};"
        : "+f"(d[0]), "+f"(d[1]), "+f"(d[2]), "+f"(d[3])
        : "r"(a[0]), "r"(a[1]), "r"(a[2]), "r"(a[3]), "r"(b0), "r"(b1));
}
__device__ __forceinline__ void cpa16(unsigned dst, const void* src) {
    asm volatile("cp.async.ca.shared.global [%0], [%1], 16;" :: "r"(dst), "l"(src));
}
__device__ __forceinline__ void cpa_commit() {
    asm volatile("cp.async.commit_group;");
}
__device__ __forceinline__ void cpa_wait0() {
    asm volatile("cp.async.wait_group 0;");
}

// ---------------- hypernet small MLPs + FiLM heads ----------------
__global__ void hyper_small(const int* __restrict__ labels,
                            const float* __restrict__ emb,
                            const float* __restrict__ hw1, const float* __restrict__ hb1,
                            const float* __restrict__ hw2, const float* __restrict__ hb2,
                            const float* __restrict__ f1w1, const float* __restrict__ f1b1,
                            const float* __restrict__ f1w2, const float* __restrict__ f1b2,
                            const float* __restrict__ f2w1, const float* __restrict__ f2b1,
                            const float* __restrict__ f2w2, const float* __restrict__ f2b2)
{
    int b = blockIdx.x;
    int t = threadIdx.x;            // 256 threads
    __shared__ float s_cond[D_];
    __shared__ float s_h1[HID];
    __shared__ float s_t[D_];

    if (t < D_) s_cond[t] = emb[(size_t)labels[b] * D_ + t];
    __syncthreads();

    {
        float a = hb1[t];
        #pragma unroll 4
        for (int k = 0; k < D_; k++) a = fmaf(s_cond[k], hw1[k * HID + t], a);
        s_h1[t] = fmaxf(a, 0.f);
    }
    __syncthreads();

    {
        float a = hb2[t];
        #pragma unroll 4
        for (int k = 0; k < HID; k++) a = fmaf(s_h1[k], hw2[k * HID + t], a);
        g_h2[b][t] = fmaxf(a, 0.f);
    }

    if (t < D_) {
        float v = f1b1[t];
        #pragma unroll 4
        for (int k = 0; k < D_; k++) v = fmaf(s_cond[k], f1w1[k * D_ + t], v);
        s_t[t] = fmaxf(v, 0.f);
    }
    __syncthreads();
    if (t < D_) {
        float v = f1b2[t];
        #pragma unroll 4
        for (int k = 0; k < D_; k++) v = fmaf(s_t[k], f1w2[k * D_ + t], v);
        if (t < C_) g_film[0][b][t] = v; else g_film[1][b][t - C_] = v;
    }
    __syncthreads();

    if (t < D_) {
        float v = f2b1[t];
        #pragma unroll 4
        for (int k = 0; k < D_; k++) v = fmaf(s_cond[k], f2w1[k * D_ + t], v);
        s_t[t] = fmaxf(v, 0.f);
    }
    __syncthreads();
    if (t < D_) {
        float v = f2b2[t];
        #pragma unroll 4
        for (int k = 0; k < D_; k++) v = fmaf(s_t[k], f2w2[k * D_ + t], v);
        if (t < C_) g_film[2][b][t] = v; else g_film[3][b][t - C_] = v;
    }
}

// ---------------- big hypernet layer -> bf16 hi/lo weight planes ----------------
__global__ void pack_weights(const float* __restrict__ hw3, const float* __restrict__ hb3)
{
    __shared__ float s_h2t[HID][B_];
    int tid = threadIdx.x;
    for (int it = 0; it < B_; it++)
        s_h2t[tid][it] = g_h2[it][tid];
    __syncthreads();

    size_t j = (size_t)blockIdx.x * 256 + tid;   // j < 147456
    float acc[B_];
    #pragma unroll
    for (int b = 0; b < B_; b++) acc[b] = 0.f;

    const float* col = hw3 + j;
    #pragma unroll 4
    for (int k = 0; k < HID; k++) {
        float w = col[(size_t)k * (2 * TOT1)];
        const float4* v = reinterpret_cast<const float4*>(&s_h2t[k][0]);
        #pragma unroll
        for (int q = 0; q < 8; q++) {
            float4 h = v[q];
            acc[4 * q + 0] = fmaf(w, h.x, acc[4 * q + 0]);
            acc[4 * q + 1] = fmaf(w, h.y, acc[4 * q + 1]);
            acc[4 * q + 2] = fmaf(w, h.z, acc[4 * q + 2]);
            acc[4 * q + 3] = fmaf(w, h.w, acc[4 * q + 3]);
        }
    }

    float bias = hb3[j];
    int which = (j >= TOT1) ? 1 : 0;
    int jj = which ? (int)j - TOT1 : (int)j;
    int co  = jj / 576;
    int rem = jj - co * 576;
    int ci  = rem / 9;
    int tap = rem - ci * 9;
    int cc  = ci >> 4;
    int cl  = ci & 15;
    int didx = ((cc * 9 + tap) * C_ + co) * 16 + cl;
    #pragma unroll
    for (int b = 0; b < B_; b++) {
        float v = acc[b] + bias;
        __nv_bfloat16 h = __float2bfloat16(v);
        __nv_bfloat16 l = __float2bfloat16(v - __bfloat162float(h));
        g_wh[which][b][didx] = h;
        g_wl[which][b][didx] = l;
    }
}

// ---------------- initial state -> bf16 planes ----------------
__global__ void init_convert(const float* __restrict__ init)
{
    int bc = blockIdx.x;                 // b*4+cc
    int b  = bc >> 2, cc = bc & 3;
    int y  = blockIdx.y * 4 + (threadIdx.x >> 6);
    int x  = threadIdx.x & 63;

    __nv_bfloat16 h[16], l[16];
    #pragma unroll
    for (int ci = 0; ci < 16; ci++) {
        float v = init[((size_t)(b * C_ + cc * 16 + ci)) * NPIX + y * HW_ + x];
        h[ci] = __float2bfloat16(v);
        l[ci] = __float2bfloat16(v - __bfloat162float(h[ci]));
    }
    size_t o = ((size_t)bc * NPIX + y * HW_ + x) * 16;
    reinterpret_cast<uint4*>(g_sh + o)[0] = reinterpret_cast<uint4*>(h)[0];
    reinterpret_cast<uint4*>(g_sh + o)[1] = reinterpret_cast<uint4*>(h)[1];
    reinterpret_cast<uint4*>(g_sl + o)[0] = reinterpret_cast<uint4*>(l)[0];
    reinterpret_cast<uint4*>(g_sl + o)[1] = reinterpret_cast<uint4*>(l)[1];
}

// ---------------- conv step: cp.async double-buffered bf16x3 tensor-core conv ----------------
// block: (ytile 0..15, b 0..31), 512 threads = 16 warps.
// Output tile: 4 rows x 64 x = 256 pixels x 64 co.
// warp (wm=wid>>2 row, wn=wid&3 co16-group): m64 (one row) x n16.
// smem per buffer: A [row6][slot66][pitch24] hi+lo; W [tap9][co64][pitch24] hi+lo.
#define PITCHB 48                       // bytes per pitch row (24 bf16)
#define SIN_PLANE_B (6 * 66 * PITCHB)   // 19008 B
#define SW_PLANE_B  (9 * 64 * PITCHB)   // 27648 B
#define BUF_B (2 * SIN_PLANE_B + 2 * SW_PLANE_B)   // 93312 B
#define SMEM_BYTES (2 * BUF_B)                     // 186624 B
#define NCHUNK_IN (6 * 66 * 2 * 2)      // 1584
#define NCHUNK_W  (9 * 64 * 2 * 2)      // 2304
#define NCHUNK    (NCHUNK_IN + NCHUNK_W)

__global__ __launch_bounds__(512, 1)
void conv_step(const float* __restrict__ init,
               const float* __restrict__ blendp,
               float* __restrict__ head,
               float* __restrict__ traj,
               int step, int isB)
{
    extern __shared__ __align__(16) char smem[];
    const unsigned sbase = smem_u32(smem);

    const int tid  = threadIdx.x;
    const int lane = tid & 31;
    const int wid  = tid >> 5;
    const int wm   = wid >> 2;         // output row 0..3
    const int wn   = wid & 3;          // co16 group 0..3
    const int b    = blockIdx.y;
    const int y0   = blockIdx.x * 4;

    const __nv_bfloat16* in_h = isB ? g_uh : g_sh;
    const __nv_bfloat16* in_l = isB ? g_ul : g_sl;
    const __nv_bfloat16* wbh  = &g_wh[isB][b][0];
    const __nv_bfloat16* wbl  = &g_wl[isB][b][0];
    const float* bsrc = (step == 0) ? init : g_X;

    // ldmatrix per-lane offsets
    const int g  = lane >> 3;
    const int r8 = lane & 7;
    unsigned aoff[4];
    #pragma unroll
    for (int t = 0; t < 4; t++)
        aoff[t] = (unsigned)((wm * 66 + t * 16 + (g & 1) * 8 + r8) * PITCHB + (g >> 1) * 16);
    const unsigned boff = (unsigned)((wn * 16 + (g >> 1) * 8 + r8) * PITCHB + (g & 1) * 16);

    float acc[4][2][4];
    #pragma unroll
    for (int t = 0; t < 4; t++)
        #pragma unroll
        for (int n = 0; n < 2; n++)
            #pragma unroll
            for (int k = 0; k < 4; k++) acc[t][n][k] = 0.f;

    // ---- fill(cc, buf): cp.async 16B chunks ----
    auto fill = [&](int cc, int buf) {
        const unsigned base = sbase + buf * BUF_B;
        #pragma unroll
        for (int it = 0; it < 8; it++) {
            int idx = tid + 512 * it;
            if (idx < NCHUNK_IN) {
                int half  = idx & 1;
                int plane = (idx >> 1) & 1;
                int rest  = idx >> 2;          // < 396
                int slot  = rest % 66;
                int row   = rest / 66;
                int gy = (y0 - 1 + row) & 63;
                int gx = (slot + 63) & 63;
                unsigned dst = base + plane * SIN_PLANE_B + (row * 66 + slot) * PITCHB + half * 16;
                const __nv_bfloat16* src =
                    (plane ? in_l : in_h) +
                    (((size_t)(b * 4 + cc) * NPIX + gy * HW_ + gx) * 16 + half * 8);
                cpa16(dst, src);
            } else if (idx < NCHUNK) {
                int c = idx - NCHUNK_IN;
                int half  = c & 1;
                int plane = (c >> 1) & 1;
                int rest  = c >> 2;            // < 576
                int co  = rest & 63;
                int tap = rest >> 6;
                unsigned dst = base + 2 * SIN_PLANE_B + plane * SW_PLANE_B +
                               (tap * 64 + co) * PITCHB + half * 16;
                const __nv_bfloat16* src =
                    (plane ? wbl : wbh) + (((cc * 9 + tap) * 64 + co) * 16 + half * 8);
                cpa16(dst, src);
            }
        }
    };

    fill(0, 0);
    cpa_commit();

    for (int cc = 0; cc < 4; cc++) {
        cpa_wait0();
        __syncthreads();
        if (cc < 3) {
            fill(cc + 1, (cc + 1) & 1);
            cpa_commit();
        }
        const unsigned bb   = sbase + (cc & 1) * BUF_B;
        const unsigned u_ih = bb;
        const unsigned u_il = bb + SIN_PLANE_B;
        const unsigned u_wh = bb + 2 * SIN_PLANE_B;
        const unsigned u_wl = bb + 2 * SIN_PLANE_B + SW_PLANE_B;

        #pragma unroll
        for (int tap = 0; tap < 9; tap++) {
            const int dy = tap / 3, dx = tap % 3;
            const unsigned ta = (unsigned)((dy * 66 + dx) * PITCHB);
            const unsigned tb = (unsigned)(tap * 64 * PITCHB);

            unsigned bh[4], bl[4];
            ldsm4(bh, u_wh + boff + tb);
            ldsm4(bl, u_wl + boff + tb);

            #pragma unroll
            for (int t = 0; t < 4; t++) {
                unsigned ah[4], al[4];
                ldsm4(ah, u_ih + aoff[t] + ta);
                ldsm4(al, u_il + aoff[t] + ta);
                // hi*hi
                mma16816(acc[t][0], ah, bh[0], bh[1]);
                mma16816(acc[t][1], ah, bh[2], bh[3]);
                // hi*lo(w)
                mma16816(acc[t][0], ah, bl[0], bl[1]);
                mma16816(acc[t][1], ah, bl[2], bl[3]);
                // lo(a)*hi
                mma16816(acc[t][0], al, bh[0], bh[1]);
                mma16816(acc[t][1], al, bh[2], bh[3]);
            }
        }
        if (cc < 3) __syncthreads();
    }

    // ---------------- epilogue ----------------
    float s = 0.f, oms = 1.f;
    if (isB) {
        s = 1.f / (1.f + expf(-blendp[0]));
        oms = 1.f - s;
    }
    const int y = y0 + wm;
    const int rbase = lane >> 2;
    const int cpair = (lane & 3) * 2;

    __nv_bfloat16* out_h = isB ? g_sh : g_uh;
    __nv_bfloat16* out_l = isB ? g_sl : g_ul;

    #pragma unroll
    for (int t = 0; t < 4; t++) {
        #pragma unroll
        for (int half = 0; half < 2; half++) {
            int px = t * 16 + rbase + 8 * half;
            #pragma unroll
            for (int n = 0; n < 2; n++) {
                int cl0 = n * 8 + cpair;
                int co0 = wn * 16 + cl0;
                float v0, v1;
                {
                    float gv0 = g_film[isB * 2][b][co0];
                    float bv0 = g_film[isB * 2 + 1][b][co0];
                    float gv1 = g_film[isB * 2][b][co0 + 1];
                    float bv1 = g_film[isB * 2 + 1][b][co0 + 1];
                    v0 = fmaxf(fmaf(gv0, acc[t][n][2 * half + 0], bv0), 0.f);
                    v1 = fmaxf(fmaf(gv1, acc[t][n][2 * half + 1], bv1), 0.f);
                }
                if (isB) {
                    size_t o0 = ((size_t)(b * C_ + co0)) * NPIX + (size_t)y * HW_ + px;
                    size_t o1 = o0 + NPIX;
                    float ng0 = fmaf(oms, bsrc[o0], s * v0);
                    float ng1 = fmaf(oms, bsrc[o1], s * v1);
                    g_X[o0] = ng0;
                    g_X[o1] = ng1;
                    v0 = ng0; v1 = ng1;
                    if (co0 < 3) {
                        float r0 = 1.f / (1.f + expf(-ng0));
                        traj[(((size_t)step * B_ + b) * 3 + co0) * NPIX + (size_t)y * HW_ + px] = r0;
                        if (step == NSTEP - 1)
                            head[((size_t)(b * 3 + co0)) * NPIX + (size_t)y * HW_ + px] = r0;
                        if (co0 + 1 < 3) {
                            float r1 = 1.f / (1.f + expf(-ng1));
                            traj[(((size_t)step * B_ + b) * 3 + co0 + 1) * NPIX + (size_t)y * HW_ + px] = r1;
                            if (step == NSTEP - 1)
                                head[((size_t)(b * 3 + co0 + 1)) * NPIX + (size_t)y * HW_ + px] = r1;
                        }
                    }
                }
                // split to bf16 hi/lo planes (next conv's input)
                __nv_bfloat16 h0 = __float2bfloat16(v0);
                __nv_bfloat16 l0 = __float2bfloat16(v0 - __bfloat162float(h0));
                __nv_bfloat16 h1 = __float2bfloat16(v1);
                __nv_bfloat16 l1 = __float2bfloat16(v1 - __bfloat162float(h1));
                size_t po = ((size_t)(b * 4 + wn) * NPIX + (size_t)y * HW_ + px) * 16 + cl0;
                __nv_bfloat162 hp; hp.x = h0; hp.y = h1;
                __nv_bfloat162 lp; lp.x = l0; lp.y = l1;
                *reinterpret_cast<__nv_bfloat162*>(out_h + po) = hp;
                *reinterpret_cast<__nv_bfloat162*>(out_l + po) = lp;
            }
        }
    }
}

// ---------------- launcher ----------------
extern "C" void kernel_launch(void* const* d_in, const int* in_sizes, int n_in,
                              void* d_out, int out_size)
{
    const int*   labels = (const int*)  d_in[0];
    const float* init   = (const float*)d_in[1];
    const float* emb    = (const float*)d_in[2];
    const float* hw1    = (const float*)d_in[3];
    const float* hb1    = (const float*)d_in[4];
    const float* hw2    = (const float*)d_in[5];
    const float* hb2    = (const float*)d_in[6];
    const float* hw3    = (const float*)d_in[7];
    const float* hb3    = (const float*)d_in[8];
    const float* f1w1   = (const float*)d_in[9];
    const float* f1b1   = (const float*)d_in[10];
    const float* f1w2   = (const float*)d_in[11];
    const float* f1b2   = (const float*)d_in[12];
    const float* f2w1   = (const float*)d_in[13];
    const float* f2b1   = (const float*)d_in[14];
    const float* f2w2   = (const float*)d_in[15];
    const float* f2b2   = (const float*)d_in[16];
    const float* blend  = (const float*)d_in[17];

    float* out  = (float*)d_out;
    float* head = out;                              // traj[-1]: [B,3,H,W]
    float* traj = out + (size_t)B_ * 3 * NPIX;      // traj:     [T,B,3,H,W]

    cudaFuncSetAttribute(conv_step, cudaFuncAttributeMaxDynamicSharedMemorySize, SMEM_BYTES);

    hyper_small<<<B_, 256>>>(labels, emb, hw1, hb1, hw2, hb2,
                             f1w1, f1b1, f1w2, f1b2, f2w1, f2b1, f2w2, f2b2);
    pack_weights<<<(2 * TOT1) / 256, 256>>>(hw3, hb3);
    init_convert<<<dim3(B_ * 4, 16), 256>>>(init);

    for (int t = 0; t < NSTEP; t++) {
        conv_step<<<dim3(16, B_), 512, SMEM_BYTES>>>(init, blend, head, traj, t, 0);
        conv_step<<<dim3(16, B_), 512, SMEM_BYTES>>>(init, blend, head, traj, t, 1);
    }
}